// round 13
// baseline (speedup 1.0000x reference)
#include <cuda_runtime.h>
#include <math.h>

// Problem constants (fixed by setup_inputs)
#define B_   64
#define S_   256
#define H_   768
#define D_   64
#define NEG_ 4

#define EPSF 1e-15f
#define BNDF (1.0f - 1e-7f)

// Scratch (device globals — no allocation allowed)
__device__ float g_u [B_ * D_];
__device__ float g_v [B_ * D_];
__device__ float g_un[B_ * NEG_ * D_];

// ---------------------------------------------------------------------------
// Stage 1: per selected row -> expmap0 -> mobius_matvec(W, .) -> scratch
// 384 blocks: [0,64) -> u via mask1, [64,128) -> v via mask2, [128,384) -> u_neg
// ---------------------------------------------------------------------------
__global__ void __launch_bounds__(256, 4)
stage1_kernel(const float* __restrict__ enc,
              const float* __restrict__ nenc,
              const float* __restrict__ m1,
              const float* __restrict__ m2,
              const float* __restrict__ mneg,
              const float* __restrict__ Wm)
{
    const int row = blockIdx.x;
    const int tid = threadIdx.x;

    const float* mask;
    const float* src;
    float*       dst;
    if (row < B_) {
        mask = m1   + (size_t)row * S_;
        src  = enc  + (size_t)row * S_ * H_;
        dst  = g_u  + row * D_;
    } else if (row < 2 * B_) {
        const int r = row - B_;
        mask = m2   + (size_t)r * S_;
        src  = enc  + (size_t)r * S_ * H_;
        dst  = g_v  + r * D_;
    } else {
        const int r = row - 2 * B_;
        mask = mneg + (size_t)r * S_;
        src  = nenc + (size_t)r * S_ * H_;
        dst  = g_un + r * D_;
    }

    __shared__ int   s_sel;
    __shared__ float s_p[H_];       // expmap0(x)
    __shared__ float s_mx[D_];      // W @ p
    __shared__ float s_red[8];
    __shared__ float s_scale[2];    // [0]=broadcast scale, [1]=xn

    // --- find one-hot index (exactly one mask element is 1.0) ---
    if (mask[tid] > 0.5f) s_sel = tid;
    __syncthreads();
    const float* x = src + (size_t)s_sel * H_;

    // --- load x, ||x||^2 ---
    float acc = 0.0f;
    #pragma unroll
    for (int i = 0; i < H_ / 256; i++) {
        float v = x[tid + i * 256];
        s_p[tid + i * 256] = v;
        acc += v * v;
    }
    #pragma unroll
    for (int o = 16; o; o >>= 1) acc += __shfl_xor_sync(0xFFFFFFFFu, acc, o);
    if ((tid & 31) == 0) s_red[tid >> 5] = acc;
    __syncthreads();
    if (tid == 0) {
        float n2 = 0.0f;
        #pragma unroll
        for (int w = 0; w < 8; w++) n2 += s_red[w];
        float n  = sqrtf(n2);
        float nc = fmaxf(n, EPSF);
        float t  = tanhf(nc);
        s_scale[0] = t / nc;   // expmap0 scale
        s_scale[1] = t;        // xn = ||p|| (== tanh(n) for n >= EPS)
    }
    __syncthreads();

    // --- p = expmap0(x) in smem ---
    const float es = s_scale[0];
    #pragma unroll
    for (int i = 0; i < H_ / 256; i++) s_p[tid + i * 256] *= es;
    __syncthreads();

    // --- mx = p @ W^T : 8 warps x 8 rows each, warp-dot over H ---
    const int warp = tid >> 5;
    const int lane = tid & 31;
    #pragma unroll
    for (int dd = 0; dd < 8; dd++) {
        const int d = warp * 8 + dd;
        const float* wrow = Wm + (size_t)d * H_;
        float a = 0.0f;
        #pragma unroll
        for (int k = lane; k < H_; k += 32)
            a = fmaf(s_p[k], __ldg(wrow + k), a);
        #pragma unroll
        for (int o = 16; o; o >>= 1) a += __shfl_xor_sync(0xFFFFFFFFu, a, o);
        if (lane == 0) s_mx[d] = a;
    }
    __syncthreads();

    // --- mobius_matvec scale: tanh(mn/xn * artanh(xn)) / mn ---
    if (tid < 32) {
        float a0 = s_mx[tid];
        float a1 = s_mx[tid + 32];
        float a  = a0 * a0 + a1 * a1;
        #pragma unroll
        for (int o = 16; o; o >>= 1) a += __shfl_xor_sync(0xFFFFFFFFu, a, o);
        if (tid == 0) {
            float mn  = sqrtf(a);
            float mnc = fmaxf(mn, EPSF);
            float xn  = fmaxf(s_scale[1], EPSF);
            float at  = atanhf(fminf(xn, BNDF));
            s_scale[0] = tanhf(mnc / xn * at) / mnc;
        }
    }
    __syncthreads();

    if (tid < D_) dst[tid] = s_scale[0] * s_mx[tid];
}

// ---------------------------------------------------------------------------
// Stage 2: per-batch epilogue (angles + distances + ns_loss), mean -> out[0]
// One block, 256 threads: 8 warps, each warp handles 8 batch rows.
// ---------------------------------------------------------------------------
__device__ __forceinline__ float warp_sum(float v) {
    #pragma unroll
    for (int o = 16; o; o >>= 1) v += __shfl_xor_sync(0xFFFFFFFFu, v, o);
    return v;
}

__global__ void __launch_bounds__(256, 1)
stage2_kernel(float* __restrict__ out)
{
    const int warp = threadIdx.x >> 5;
    const int lane = threadIdx.x & 31;
    __shared__ float s_loss[B_];
    __shared__ float s_part[2];

    for (int b = warp; b < B_; b += 8) {
        const float* u = g_u + b * D_;
        const float* v = g_v + b * D_;
        const float u0 = u[lane], u1 = u[lane + 32];
        const float v0 = v[lane], v1 = v[lane + 32];

        float x2 = warp_sum(u0 * u0 + u1 * u1);
        float y2 = warp_sum(v0 * v0 + v1 * v1);
        float xy = warp_sum(u0 * v0 + u1 * v1);
        float eu = warp_sum((u0 - v0) * (u0 - v0) + (u1 - v1) * (u1 - v1));

        // ---- dist(u, v): mobius_add(-u, v) ----
        float ca  = 1.0f - 2.0f * xy + y2;           // (1 + 2<a,y> + y2), a=-u
        float cb  = 1.0f - x2;                        // (1 - a2)
        float den = fmaxf(1.0f - 2.0f * xy + x2 * y2, EPSF);
        float n0  = ca * (-u0) + cb * v0;
        float n1  = ca * (-u1) + cb * v1;
        float ns  = warp_sum(n0 * n0 + n1 * n1);
        float dn  = sqrtf(ns) / den;
        float duv = 2.0f * atanhf(fminf(dn, BNDF));

        // ---- angles ----
        float nu     = sqrtf(x2);
        float nv     = sqrtf(y2);
        float euclid = sqrtf(eu);
        float rad    = fmaxf(1.0f + x2 * y2 - 2.0f * xy, EPSF);
        float aden   = fmaxf(nv * euclid * sqrtf(rad), EPSF);
        float cosang = (xy * (1.0f + y2) - y2 * (1.0f + x2)) / aden;
        cosang       = fminf(fmaxf(cosang, -BNDF), BNDF);
        float ang    = acosf(cosang);
        (void)nu;

        // ---- negative-sample distances ----
        float Z1 = 0.0f;
        #pragma unroll
        for (int j = 0; j < NEG_; j++) {
            const float* un = g_un + (size_t)(b * NEG_ + j) * D_;
            const float w0 = un[lane], w1 = un[lane + 32];
            float yn2 = warp_sum(w0 * w0 + w1 * w1);
            float xyn = warp_sum(u0 * w0 + u1 * w1);
            float cA  = 1.0f - 2.0f * xyn + yn2;
            float cB  = 1.0f - x2;
            float dd  = fmaxf(1.0f - 2.0f * xyn + x2 * yn2, EPSF);
            float m0  = cA * (-u0) + cB * w0;
            float m1  = cA * (-u1) + cB * w1;
            float ms  = warp_sum(m0 * m0 + m1 * m1);
            float dnn = sqrtf(ms) / dd;
            float dj  = 2.0f * atanhf(fminf(dnn, BNDF));
            Z1 += expf(-dj);
        }

        float expneg = expf(-duv);
        float nsl    = -logf(expneg / (Z1 + expneg));
        if (lane == 0) s_loss[b] = ang + nsl;   // 2*(1-0.5)*ang + 2*0.5*nsl
    }
    __syncthreads();

    // reduce 64 per-batch losses -> mean
    if (threadIdx.x < 64) {
        float l = warp_sum(s_loss[threadIdx.x]);
        if (lane == 0) s_part[threadIdx.x >> 5] = l;
    }
    __syncthreads();
    if (threadIdx.x == 0)
        out[0] = (s_part[0] + s_part[1]) * (1.0f / (float)B_);
}

// ---------------------------------------------------------------------------
extern "C" void kernel_launch(void* const* d_in, const int* in_sizes, int n_in,
                              void* d_out, int out_size)
{
    const float* enc  = (const float*)d_in[0];  // [64,256,768]
    const float* nenc = (const float*)d_in[1];  // [256,256,768]
    const float* m1   = (const float*)d_in[2];  // [64,256,1]
    const float* m2   = (const float*)d_in[3];  // [64,256,1]
    const float* mneg = (const float*)d_in[4];  // [256,256,1]
    const float* Wm   = (const float*)d_in[5];  // [64,768]
    float* out = (float*)d_out;

    stage1_kernel<<<2 * B_ + B_ * NEG_, 256>>>(enc, nenc, m1, m2, mneg, Wm);
    stage2_kernel<<<1, 256>>>(out);
}

// round 14
// speedup vs baseline: 2.0909x; 2.0909x over previous
#include <cuda_runtime.h>
#include <math.h>

// Problem constants (fixed by setup_inputs)
#define B_   64
#define S_   256
#define H_   768
#define D_   64
#define NEG_ 4

#define EPSF 1e-15f
#define BNDF (1.0f - 1e-7f)

// Scratch (device globals — no allocation allowed)
__device__ float g_u [B_ * D_];
__device__ float g_v [B_ * D_];
__device__ float g_un[B_ * NEG_ * D_];

// ---------------------------------------------------------------------------
// Stage 1: 96 blocks x 4 rows. Row space [0,384):
//   [0,64)   -> u via mask1,  [64,128) -> v via mask2,  [128,384) -> u_neg
// Per row: select one-hot token, expmap0, mobius_matvec(W, .) -> scratch.
// 4 rows share each W element load (register reuse).
// ---------------------------------------------------------------------------
__global__ void __launch_bounds__(256, 4)
stage1_kernel(const float* __restrict__ enc,
              const float* __restrict__ nenc,
              const float* __restrict__ m1,
              const float* __restrict__ m2,
              const float* __restrict__ mneg,
              const float* __restrict__ Wm)
{
    const int base = blockIdx.x * 4;
    const int tid  = threadIdx.x;
    const int warp = tid >> 5;
    const int lane = tid & 31;

    __shared__ float s_p[4][H_];      // expmap0(x) per row
    __shared__ float s_mx[4][D_];     // W @ p per row
    __shared__ int   s_sel[4];
    __shared__ float s_red[4][8];
    __shared__ float s_scale[4][2];   // [r][0]=scale, [r][1]=xn

    const float* mask[4];
    const float* src[4];
    float*       dst[4];
    #pragma unroll
    for (int r = 0; r < 4; r++) {
        const int row = base + r;
        if (row < B_) {
            mask[r] = m1   + (size_t)row * S_;
            src[r]  = enc  + (size_t)row * S_ * H_;
            dst[r]  = g_u  + row * D_;
        } else if (row < 2 * B_) {
            const int q = row - B_;
            mask[r] = m2   + (size_t)q * S_;
            src[r]  = enc  + (size_t)q * S_ * H_;
            dst[r]  = g_v  + q * D_;
        } else {
            const int q = row - 2 * B_;
            mask[r] = mneg + (size_t)q * S_;
            src[r]  = nenc + (size_t)q * S_ * H_;
            dst[r]  = g_un + q * D_;
        }
    }

    // --- find one-hot indices ---
    #pragma unroll
    for (int r = 0; r < 4; r++)
        if (mask[r][tid] > 0.5f) s_sel[r] = tid;
    __syncthreads();

    // --- load selected rows + squared norms ---
    float acc[4] = {0.f, 0.f, 0.f, 0.f};
    #pragma unroll
    for (int r = 0; r < 4; r++) {
        const float* x = src[r] + (size_t)s_sel[r] * H_;
        #pragma unroll
        for (int i = 0; i < H_ / 256; i++) {
            float v = x[tid + i * 256];
            s_p[r][tid + i * 256] = v;
            acc[r] += v * v;
        }
    }
    #pragma unroll
    for (int o = 16; o; o >>= 1) {
        #pragma unroll
        for (int r = 0; r < 4; r++)
            acc[r] += __shfl_xor_sync(0xFFFFFFFFu, acc[r], o);
    }
    if (lane == 0) {
        #pragma unroll
        for (int r = 0; r < 4; r++) s_red[r][warp] = acc[r];
    }
    __syncthreads();
    if (tid < 4) {
        float n2 = 0.f;
        #pragma unroll
        for (int w = 0; w < 8; w++) n2 += s_red[tid][w];
        float n  = sqrtf(n2);
        float nc = fmaxf(n, EPSF);
        float t  = tanhf(nc);
        s_scale[tid][0] = t / nc;   // expmap0 scale
        s_scale[tid][1] = t;        // xn = ||p||
    }
    __syncthreads();

    // --- p = expmap0(x) ---
    {
        float es0 = s_scale[0][0], es1 = s_scale[1][0];
        float es2 = s_scale[2][0], es3 = s_scale[3][0];
        #pragma unroll
        for (int i = 0; i < H_ / 256; i++) {
            const int k = tid + i * 256;
            s_p[0][k] *= es0;  s_p[1][k] *= es1;
            s_p[2][k] *= es2;  s_p[3][k] *= es3;
        }
    }
    __syncthreads();

    // --- mx[r] = p[r] @ W^T : warp handles 8 W rows, W element reused x4 ---
    {
        float a[8][4];
        #pragma unroll
        for (int dd = 0; dd < 8; dd++)
            #pragma unroll
            for (int r = 0; r < 4; r++) a[dd][r] = 0.f;

        const float* wbase = Wm + (size_t)(warp * 8) * H_;
        #pragma unroll
        for (int i = 0; i < H_ / 32; i++) {
            const int k = lane + i * 32;
            const float p0 = s_p[0][k], p1 = s_p[1][k];
            const float p2 = s_p[2][k], p3 = s_p[3][k];
            #pragma unroll
            for (int dd = 0; dd < 8; dd++) {
                const float wv = __ldg(wbase + (size_t)dd * H_ + k);
                a[dd][0] = fmaf(p0, wv, a[dd][0]);
                a[dd][1] = fmaf(p1, wv, a[dd][1]);
                a[dd][2] = fmaf(p2, wv, a[dd][2]);
                a[dd][3] = fmaf(p3, wv, a[dd][3]);
            }
        }
        #pragma unroll
        for (int o = 16; o; o >>= 1)
            #pragma unroll
            for (int dd = 0; dd < 8; dd++)
                #pragma unroll
                for (int r = 0; r < 4; r++)
                    a[dd][r] += __shfl_xor_sync(0xFFFFFFFFu, a[dd][r], o);
        if (lane == 0) {
            #pragma unroll
            for (int dd = 0; dd < 8; dd++)
                #pragma unroll
                for (int r = 0; r < 4; r++)
                    s_mx[r][warp * 8 + dd] = a[dd][r];
        }
    }
    __syncthreads();

    // --- mobius_matvec scale per row: warp r handles row r ---
    if (warp < 4) {
        float a0 = s_mx[warp][lane];
        float a1 = s_mx[warp][lane + 32];
        float a  = a0 * a0 + a1 * a1;
        #pragma unroll
        for (int o = 16; o; o >>= 1) a += __shfl_xor_sync(0xFFFFFFFFu, a, o);
        if (lane == 0) {
            float mn  = sqrtf(a);
            float mnc = fmaxf(mn, EPSF);
            float xn  = fmaxf(s_scale[warp][1], EPSF);
            float at  = atanhf(fminf(xn, BNDF));
            s_scale[warp][0] = tanhf(mnc / xn * at) / mnc;
        }
    }
    __syncthreads();

    // --- write: 256 threads = 4 rows x 64 dims ---
    {
        const int r = tid >> 6;
        const int d = tid & 63;
        dst[r][d] = s_scale[r][0] * s_mx[r][d];
    }
}

// ---------------------------------------------------------------------------
// Stage 2: per-batch epilogue, algebraically collapsed to dot products.
// 1 block x 1024 threads = 32 warps; each warp handles rows w and w+32.
// All vector norms come from: x2, y2, xy, yn2[j], xyn[j] (11 butterflies,
// all independent). The 5 Poincare distances are computed in parallel on
// lanes 0..4 of the warp.
// ---------------------------------------------------------------------------
__global__ void __launch_bounds__(1024, 1)
stage2_kernel(float* __restrict__ out)
{
    const int warp = threadIdx.x >> 5;
    const int lane = threadIdx.x & 31;
    __shared__ float s_loss[B_];
    __shared__ float s_part[2];

    #pragma unroll
    for (int half = 0; half < 2; half++) {
        const int b = warp + half * 32;
        const float* u  = g_u  + b * D_;
        const float* v  = g_v  + b * D_;
        const float* un = g_un + (size_t)b * NEG_ * D_;

        const float u0 = u[lane],        u1 = u[lane + 32];
        const float v0 = v[lane],        v1 = v[lane + 32];
        const float w00 = un[lane],       w01 = un[lane + 32];
        const float w10 = un[64 + lane],  w11 = un[96 + lane];
        const float w20 = un[128 + lane], w21 = un[160 + lane];
        const float w30 = un[192 + lane], w31 = un[224 + lane];

        float x2 = u0 * u0 + u1 * u1;
        float y2 = v0 * v0 + v1 * v1;
        float xy = u0 * v0 + u1 * v1;
        float n0 = w00 * w00 + w01 * w01;
        float n1 = w10 * w10 + w11 * w11;
        float n2 = w20 * w20 + w21 * w21;
        float n3 = w30 * w30 + w31 * w31;
        float c0 = u0 * w00 + u1 * w01;
        float c1 = u0 * w10 + u1 * w11;
        float c2 = u0 * w20 + u1 * w21;
        float c3 = u0 * w30 + u1 * w31;

        #pragma unroll
        for (int o = 16; o; o >>= 1) {
            x2 += __shfl_xor_sync(0xFFFFFFFFu, x2, o);
            y2 += __shfl_xor_sync(0xFFFFFFFFu, y2, o);
            xy += __shfl_xor_sync(0xFFFFFFFFu, xy, o);
            n0 += __shfl_xor_sync(0xFFFFFFFFu, n0, o);
            n1 += __shfl_xor_sync(0xFFFFFFFFu, n1, o);
            n2 += __shfl_xor_sync(0xFFFFFFFFu, n2, o);
            n3 += __shfl_xor_sync(0xFFFFFFFFu, n3, o);
            c0 += __shfl_xor_sync(0xFFFFFFFFu, c0, o);
            c1 += __shfl_xor_sync(0xFFFFFFFFu, c1, o);
            c2 += __shfl_xor_sync(0xFFFFFFFFu, c2, o);
            c3 += __shfl_xor_sync(0xFFFFFFFFu, c3, o);
        }

        // Per-lane distance: lanes 0..3 -> negatives, lanes >=4 -> d(u,v).
        float A2, XY;
        if      (lane == 0) { A2 = n0; XY = c0; }
        else if (lane == 1) { A2 = n1; XY = c1; }
        else if (lane == 2) { A2 = n2; XY = c2; }
        else if (lane == 3) { A2 = n3; XY = c3; }
        else                { A2 = y2; XY = xy; }

        // ||mobius_add(-u, y)||^2 via dot-product algebra:
        //   cA = 1 - 2<u,y> + ||y||^2,  cB = 1 - ||u||^2
        //   ms = cA^2 x2 - 2 cA cB XY + cB^2 A2
        const float cA  = 1.0f - 2.0f * XY + A2;
        const float cB  = 1.0f - x2;
        const float den = fmaxf(1.0f - 2.0f * XY + x2 * A2, EPSF);
        float ms = cA * cA * x2 - 2.0f * cA * cB * XY + cB * cB * A2;
        ms = fmaxf(ms, 0.0f);
        const float dn = sqrtf(ms) / den;
        const float d  = 2.0f * atanhf(fminf(dn, BNDF));
        const float e  = expf(-d);

        const float Z1 = __shfl_sync(0xFFFFFFFFu, e, 0)
                       + __shfl_sync(0xFFFFFFFFu, e, 1)
                       + __shfl_sync(0xFFFFFFFFu, e, 2)
                       + __shfl_sync(0xFFFFFFFFu, e, 3);
        const float expneg = __shfl_sync(0xFFFFFFFFu, e, 4);

        // angle (redundant across lanes, overlaps with distance chain)
        const float euclid = sqrtf(fmaxf(x2 + y2 - 2.0f * xy, 0.0f));
        const float rad    = fmaxf(1.0f + x2 * y2 - 2.0f * xy, EPSF);
        const float aden   = fmaxf(sqrtf(y2) * euclid * sqrtf(rad), EPSF);
        float cosang = (xy * (1.0f + y2) - y2 * (1.0f + x2)) / aden;
        cosang = fminf(fmaxf(cosang, -BNDF), BNDF);
        const float ang = acosf(cosang);

        const float nsl = -logf(expneg / (Z1 + expneg));
        if (lane == 0) s_loss[b] = ang + nsl;   // 2(1-a)ang + 2a nsl, a=0.5
    }
    __syncthreads();

    if (threadIdx.x < 64) {
        float l = s_loss[threadIdx.x];
        #pragma unroll
        for (int o = 16; o; o >>= 1) l += __shfl_xor_sync(0xFFFFFFFFu, l, o);
        if (lane == 0) s_part[threadIdx.x >> 5] = l;
    }
    __syncthreads();
    if (threadIdx.x == 0)
        out[0] = (s_part[0] + s_part[1]) * (1.0f / (float)B_);
}

// ---------------------------------------------------------------------------
extern "C" void kernel_launch(void* const* d_in, const int* in_sizes, int n_in,
                              void* d_out, int out_size)
{
    const float* enc  = (const float*)d_in[0];  // [64,256,768]
    const float* nenc = (const float*)d_in[1];  // [256,256,768]
    const float* m1   = (const float*)d_in[2];  // [64,256,1]
    const float* m2   = (const float*)d_in[3];  // [64,256,1]
    const float* mneg = (const float*)d_in[4];  // [256,256,1]
    const float* Wm   = (const float*)d_in[5];  // [64,768]
    float* out = (float*)d_out;

    stage1_kernel<<<(2 * B_ + B_ * NEG_) / 4, 256>>>(enc, nenc, m1, m2, mneg, Wm);
    stage2_kernel<<<1, 1024>>>(out);
}